// round 12
// baseline (speedup 1.0000x reference)
#include <cuda_runtime.h>
#include <cstdint>

// InverseHaarTransform collapsed to a separable 3x3 stencil on the 512-res
// input, band-pair fused:
//   P = sA*Lh(b0) + 0.5*sC*Gh(b2)   (vertical L applies)
//   Q = sB*Lh(b1) + 0.5*sD*Gh(b3)   (vertical G applies)
// Per input row y -> output rows 2y, 2y+1 (see emit code).
//
// R12: symmetric DMA. Reads: R10's cp.async.bulk ring (4 slots x 16KB,
// mbarrier expect_tx). Writes: per stage, 4 output rows (16KB contiguous in
// GMEM) staged in smem and stored with ONE cp.async.bulk.global 16KB copy
// (2 out slots, drain via cp.async.bulk.wait_group.read). Occ 2 (96KB smem).

#define YS    32
#define NP    (YS / 2)          // steady stages 1..16; stage 0 in prologue
#define H_IN  512
#define W_IN  512
#define SLOTF (4 * 2 * W_IN)    // input slot floats = 16KB [band][row01][512]
#define DEPTH 4
#define OSLOTF (4 * 1024)       // output slot floats = 16KB [4 rows][1024]
#define STAGE_BYTES (SLOTF * 4)

extern __shared__ float sm[];   // input: 4*SLOTF ; output: 2*OSLOTF  = 96KB

__global__ __launch_bounds__(256, 2)
void ihaar_kernel(const float* __restrict__ x,
                  const float* __restrict__ f0,
                  const float* __restrict__ f1,
                  const float* __restrict__ f2,
                  const float* __restrict__ f3,
                  float* __restrict__ out)
{
    __shared__ __align__(8) unsigned long long mbar[DEPTH];

    const int tx = threadIdx.x;           // owns input cols 2tx, 2tx+1
    const int z  = blockIdx.z;            // b*3 + c
    const int b  = z / 3;
    const int cc = z - 3 * b;
    const int y0 = blockIdx.y * YS;

    const int  x2 = tx * 2;
    const int  xm = (x2 == 0) ? 0 : (x2 - 1);
    const int  xp = (x2 + 2 > W_IN - 1) ? (W_IN - 1) : (x2 + 2);
    const bool xe = (x2 == 0);

    const float* pb0 = x + ((size_t)(b * 12 + 0 + cc) << 18);
    const float* pb1 = x + ((size_t)(b * 12 + 3 + cc) << 18);
    const float* pb2 = x + ((size_t)(b * 12 + 6 + cc) << 18);
    const float* pb3 = x + ((size_t)(b * 12 + 9 + cc) << 18);
    float* op = out + ((size_t)z << 20);

    const float sA = __ldg(f0), sB = __ldg(f1), sC = __ldg(f2), sD = __ldg(f3);
    const float wPle = sA,         wPge = 0.5f  * sC;
    const float wPlo = 0.25f * sA, wPgo = 0.25f * sC;
    const float wQle = sB,         wQge = 0.5f  * sD;
    const float wQlo = 0.25f * sB, wQgo = 0.25f * sD;

    const uint32_t smem_u32 = (uint32_t)__cvta_generic_to_shared(sm);
    const uint32_t mb_u32   = (uint32_t)__cvta_generic_to_shared(mbar);

    if (tx == 0) {
#pragma unroll
        for (int s = 0; s < DEPTH; ++s)
            asm volatile("mbarrier.init.shared.b64 [%0], %1;"
                         :: "r"(mb_u32 + 8 * s), "r"(1));
    }
    __syncthreads();

    float Pe[3][2], Po[3][2], Qe[3][2], Qo[3][2];

    // Stage p loads input rows (y0-1+2p, y0+2p), clamped, into slot p&3.
    auto issue = [&](int p) {
        if (tx != 0) return;
        const int slot = p & 3;
        const uint32_t mba = mb_u32 + 8 * slot;
        asm volatile("mbarrier.arrive.expect_tx.shared.b64 _, [%0], %1;"
                     :: "r"(mba), "r"((uint32_t)STAGE_BYTES) : "memory");
        int r0 = y0 - 1 + 2 * p;
        int rA = r0 < 0 ? 0 : (r0 > H_IN - 1 ? H_IN - 1 : r0);
        int rB = r0 + 1 > H_IN - 1 ? H_IN - 1 : r0 + 1;
        const float* const pbs[4] = { pb0, pb1, pb2, pb3 };
        if (rB == rA + 1) {
#pragma unroll
            for (int k = 0; k < 4; ++k) {
                uint32_t d0 = smem_u32
                    + (uint32_t)(slot * SLOTF + k * (2 * W_IN)) * 4u;
                asm volatile(
                    "cp.async.bulk.shared::cluster.global.mbarrier::complete_tx::bytes"
                    " [%0], [%1], %2, [%3];"
                    :: "r"(d0), "l"(pbs[k] + (size_t)rA * W_IN),
                       "r"((uint32_t)(2 * W_IN * 4)), "r"(mba) : "memory");
            }
        } else {
#pragma unroll
            for (int k = 0; k < 4; ++k) {
                uint32_t d0 = smem_u32
                    + (uint32_t)(slot * SLOTF + k * (2 * W_IN)) * 4u;
                uint32_t d1 = d0 + (uint32_t)W_IN * 4u;
                asm volatile(
                    "cp.async.bulk.shared::cluster.global.mbarrier::complete_tx::bytes"
                    " [%0], [%1], %2, [%3];"
                    :: "r"(d0), "l"(pbs[k] + (size_t)rA * W_IN),
                       "r"((uint32_t)(W_IN * 4)), "r"(mba) : "memory");
                asm volatile(
                    "cp.async.bulk.shared::cluster.global.mbarrier::complete_tx::bytes"
                    " [%0], [%1], %2, [%3];"
                    :: "r"(d1), "l"(pbs[k] + (size_t)rB * W_IN),
                       "r"((uint32_t)(W_IN * 4)), "r"(mba) : "memory");
            }
        }
    };

    auto waitstage = [&](int p) {
        const uint32_t mba = mb_u32 + 8 * (p & 3);
        const uint32_t par = (uint32_t)((p >> 2) & 1);
        uint32_t done;
        asm volatile(
            "{\n\t.reg .pred P;\n\t"
            "mbarrier.try_wait.parity.shared.b64 P, [%1], %2;\n\t"
            "selp.b32 %0, 1, 0, P;\n\t}"
            : "=r"(done) : "r"(mba), "r"(par) : "memory");
        while (!done) {
            asm volatile(
                "{\n\t.reg .pred P;\n\t"
                "mbarrier.try_wait.parity.shared.b64 P, [%1], %2, 0x989680;\n\t"
                "selp.b32 %0, 1, 0, P;\n\t}"
                : "=r"(done) : "r"(mba), "r"(par) : "memory");
        }
    };

    // Band k, row-half RH at slot*SLOTF + k*1024 + RH*512.
#define BUILD(W, SLOT, RH) do {                                                \
    const float* base_ = &sm[(SLOT) * SLOTF + (RH) * W_IN];                    \
    const float* r0_ = base_;                                                  \
    const float* r1_ = base_ + 2 * W_IN;                                       \
    const float* r2_ = base_ + 4 * W_IN;                                       \
    const float* r3_ = base_ + 6 * W_IN;                                       \
    float2 v0 = *(const float2*)(r0_ + x2); float v0m = r0_[xm], v0p = r0_[xp];\
    float2 v1 = *(const float2*)(r1_ + x2); float v1m = r1_[xm], v1p = r1_[xp];\
    float2 v2 = *(const float2*)(r2_ + x2); float v2m = r2_[xm], v2p = r2_[xp];\
    float2 v3 = *(const float2*)(r3_ + x2); float v3m = r3_[xm], v3p = r3_[xp];\
    float lhe0a = xe ? v0.x : (v0m + v0.x);                                    \
    float lhe0b = v0.x + v0.y;                                                 \
    float lho0a = fmaf(6.f, v0.x, v0m + v0.y);                                 \
    float lho0b = fmaf(6.f, v0.y, v0.x + v0p);                                 \
    float ghe2a = xe ? (-2.f * v2.x) : (v2m - v2.x);                           \
    float ghe2b = v2.x - v2.y;                                                 \
    float gho2a = v2m - v2.y;                                                  \
    float gho2b = v2.x - v2p;                                                  \
    Pe[W][0] = fmaf(wPle, lhe0a, wPge * ghe2a);                                \
    Pe[W][1] = fmaf(wPle, lhe0b, wPge * ghe2b);                                \
    Po[W][0] = fmaf(wPlo, lho0a, wPgo * gho2a);                                \
    Po[W][1] = fmaf(wPlo, lho0b, wPgo * gho2b);                                \
    float lhe1a = xe ? v1.x : (v1m + v1.x);                                    \
    float lhe1b = v1.x + v1.y;                                                 \
    float lho1a = fmaf(6.f, v1.x, v1m + v1.y);                                 \
    float lho1b = fmaf(6.f, v1.y, v1.x + v1p);                                 \
    float ghe3a = xe ? (-2.f * v3.x) : (v3m - v3.x);                           \
    float ghe3b = v3.x - v3.y;                                                 \
    float gho3a = v3m - v3.y;                                                  \
    float gho3b = v3.x - v3p;                                                  \
    Qe[W][0] = fmaf(wQle, lhe1a, wQge * ghe3a);                                \
    Qe[W][1] = fmaf(wQle, lhe1b, wQge * ghe3b);                                \
    Qo[W][0] = fmaf(wQlo, lho1a, wQgo * gho3a);                                \
    Qo[W][1] = fmaf(wQlo, lho1b, wQgo * gho3b);                                \
} while (0)

    // Compute output rows for window center; store into out slot rows RP*2,
    // RP*2+1 (smem layout mirrors GMEM: 4 consecutive 1024-f32 rows).
#define EMIT_S(OSL, RP, TOP) do {                                              \
    float oee[2], oeo[2], ooe[2], ooo[2];                                      \
    _Pragma("unroll")                                                          \
    for (int c = 0; c < 2; ++c) {                                              \
        if (TOP) {                                                             \
            oee[c] = Pe[1][c] - Qe[1][c];                                      \
            oeo[c] = Po[1][c] - Qo[1][c];                                      \
        } else {                                                               \
            oee[c] = fmaf(0.5f, Qe[0][c] - Qe[1][c], Pe[0][c] + Pe[1][c]);     \
            oeo[c] = fmaf(0.5f, Qo[0][c] - Qo[1][c], Po[0][c] + Po[1][c]);     \
        }                                                                      \
        ooe[c] = 0.25f * (fmaf(6.f, Pe[1][c], Pe[0][c] + Pe[2][c])             \
                          + (Qe[0][c] - Qe[2][c]));                            \
        ooo[c] = 0.25f * (fmaf(6.f, Po[1][c], Po[0][c] + Po[2][c])             \
                          + (Qo[0][c] - Qo[2][c]));                            \
    }                                                                          \
    float* so = &sm[DEPTH * SLOTF + (OSL) * OSLOTF + (RP) * 2048 + 4 * tx];    \
    *(float4*)(so)        = make_float4(oee[0], oeo[0], oee[1], oeo[1]);       \
    *(float4*)(so + 1024) = make_float4(ooe[0], ooo[0], ooe[1], ooo[1]);       \
} while (0)

    auto shiftw = [&]() {
#pragma unroll
        for (int c = 0; c < 2; ++c) {
            Pe[0][c] = Pe[1][c]; Pe[1][c] = Pe[2][c];
            Po[0][c] = Po[1][c]; Po[1][c] = Po[2][c];
            Qe[0][c] = Qe[1][c]; Qe[1][c] = Qe[2][c];
            Qo[0][c] = Qo[1][c]; Qo[1][c] = Qo[2][c];
        }
    };

    // ---- prologue: stages 0,1,2 in flight; consume stage 0 (rows y0-1, y0)
    issue(0);
    issue(1);
    issue(2);
    waitstage(0);
    BUILD(0, 0, 0);
    BUILD(1, 0, 1);

    const bool topstrip = (y0 == 0);

    for (int p = 1; p <= NP; ++p) {
        waitstage(p);

        // Out slot (p&1) is reused from stage p-2: ensure that bulk store's
        // smem reads completed (<=1 outstanding group = stage p-1's).
        if (tx == 0)
            asm volatile("cp.async.bulk.wait_group.read 1;" ::: "memory");
        __syncthreads();   // broadcast drain; also orders input-slot reads

        const int slot = p & 3;
        const int oslot = p & 1;
        const int y = y0 + 2 * p - 2;

        BUILD(2, slot, 0);
        if (topstrip && p == 1) { EMIT_S(oslot, 0, true); }
        else                    { EMIT_S(oslot, 0, false); }
        shiftw();

        BUILD(2, slot, 1);
        EMIT_S(oslot, 1, false);
        shiftw();

        asm volatile("fence.proxy.async.shared::cta;" ::: "memory");
        __syncthreads();

        if (tx == 0) {
            uint32_t so = smem_u32
                + (uint32_t)(DEPTH * SLOTF + oslot * OSLOTF) * 4u;
            asm volatile(
                "cp.async.bulk.global.shared::cta.bulk_group [%0], [%1], %2;"
                :: "l"(op + (size_t)(2 * y) * 1024), "r"(so),
                   "r"((uint32_t)(OSLOTF * 4)) : "memory");
            asm volatile("cp.async.bulk.commit_group;" ::: "memory");
        }

        // Input slot (p+2)&3 == (p-2)&3: reads done in iter p-2, ordered by
        // the barriers above.
        if (p + 2 <= NP) issue(p + 2);
    }

    if (tx == 0)
        asm volatile("cp.async.bulk.wait_group 0;" ::: "memory");
#undef BUILD
#undef EMIT_S
}

extern "C" void kernel_launch(void* const* d_in, const int* in_sizes, int n_in,
                              void* d_out, int out_size)
{
    int ix = 0;
    for (int i = 0; i < n_in; ++i)
        if (in_sizes[i] > 64) { ix = i; break; }
    const float* xin = (const float*)d_in[ix];
    const float* f[4];
    int j = 0;
    for (int i = 0; i < n_in && j < 4; ++i)
        if (i != ix) f[j++] = (const float*)d_in[i];

    const int smem_bytes = (DEPTH * SLOTF + 2 * OSLOTF) * (int)sizeof(float);
    cudaFuncSetAttribute(ihaar_kernel,
                         cudaFuncAttributeMaxDynamicSharedMemorySize,
                         smem_bytes);

    dim3 block(256, 1, 1);
    dim3 grid(1, H_IN / YS, 48);
    ihaar_kernel<<<grid, block, smem_bytes>>>(
        xin, f[0], f[1], f[2], f[3], (float*)d_out);
}

// round 13
// speedup vs baseline: 1.0758x; 1.0758x over previous
#include <cuda_runtime.h>
#include <cstdint>

// InverseHaarTransform collapsed to a separable 3x3 stencil on the 512-res
// input, band-pair fused:
//   P = sA*Lh(b0) + 0.5*sC*Gh(b2)   (vertical L applies)
//   Q = sB*Lh(b1) + 0.5*sD*Gh(b3)   (vertical G applies)
// Per input row y -> output rows 2y, 2y+1 (see emit()).
//
// R13: R10 (bulk-copy DMA ring, 4 slots / 64KB, 3 stages in flight, one CTA
// barrier per stage, band-major fused 4KB copies) with YS=16 tiles
// (grid 1536) to shrink the CTA-tail quantization loss (T_CTA ~16us).

#define YS    16
#define NP    (YS / 2)          // steady stages 1..8; stage 0 in prologue
#define H_IN  512
#define W_IN  512
#define SLOTF (4 * 2 * W_IN)    // floats per slot = 16KB  [band][row01][512]
#define DEPTH 4
#define STAGE_BYTES (SLOTF * 4)

extern __shared__ float sm[];   // [4][4][2][512] = 64KB

__global__ __launch_bounds__(256, 3)
void ihaar_kernel(const float* __restrict__ x,
                  const float* __restrict__ f0,
                  const float* __restrict__ f1,
                  const float* __restrict__ f2,
                  const float* __restrict__ f3,
                  float* __restrict__ out)
{
    __shared__ __align__(8) unsigned long long mbar[DEPTH];

    const int tx = threadIdx.x;           // owns input cols 2tx, 2tx+1
    const int z  = blockIdx.z;            // b*3 + c
    const int b  = z / 3;
    const int cc = z - 3 * b;
    const int y0 = blockIdx.y * YS;

    const int  x2 = tx * 2;
    const int  xm = (x2 == 0) ? 0 : (x2 - 1);
    const int  xp = (x2 + 2 > W_IN - 1) ? (W_IN - 1) : (x2 + 2);
    const bool xe = (x2 == 0);

    const float* pb0 = x + ((size_t)(b * 12 + 0 + cc) << 18);
    const float* pb1 = x + ((size_t)(b * 12 + 3 + cc) << 18);
    const float* pb2 = x + ((size_t)(b * 12 + 6 + cc) << 18);
    const float* pb3 = x + ((size_t)(b * 12 + 9 + cc) << 18);
    float* op = out + ((size_t)z << 20);

    const float sA = __ldg(f0), sB = __ldg(f1), sC = __ldg(f2), sD = __ldg(f3);
    const float wPle = sA,         wPge = 0.5f  * sC;
    const float wPlo = 0.25f * sA, wPgo = 0.25f * sC;
    const float wQle = sB,         wQge = 0.5f  * sD;
    const float wQlo = 0.25f * sB, wQgo = 0.25f * sD;

    const uint32_t smem_u32 = (uint32_t)__cvta_generic_to_shared(sm);
    const uint32_t mb_u32   = (uint32_t)__cvta_generic_to_shared(mbar);

    if (tx == 0) {
#pragma unroll
        for (int s = 0; s < DEPTH; ++s)
            asm volatile("mbarrier.init.shared.b64 [%0], %1;"
                         :: "r"(mb_u32 + 8 * s), "r"(1));
    }
    __syncthreads();

    float Pe[3][2], Po[3][2], Qe[3][2], Qo[3][2];

    // Stage p loads input rows (y0-1+2p, y0+2p), clamped, into slot p&3.
    // Band-major slot: band k at k*1024 floats, its two rows contiguous.
    // Interior stages (rB == rA+1): one fused 4KB copy per band.
    auto issue = [&](int p) {
        if (tx != 0) return;
        const int slot = p & 3;
        const uint32_t mba = mb_u32 + 8 * slot;
        asm volatile("mbarrier.arrive.expect_tx.shared.b64 _, [%0], %1;"
                     :: "r"(mba), "r"((uint32_t)STAGE_BYTES) : "memory");
        int r0 = y0 - 1 + 2 * p;
        int rA = r0 < 0 ? 0 : (r0 > H_IN - 1 ? H_IN - 1 : r0);
        int rB = r0 + 1 > H_IN - 1 ? H_IN - 1 : r0 + 1;
        const float* const pbs[4] = { pb0, pb1, pb2, pb3 };
        if (rB == rA + 1) {
#pragma unroll
            for (int k = 0; k < 4; ++k) {
                uint32_t d0 = smem_u32
                    + (uint32_t)(slot * SLOTF + k * (2 * W_IN)) * 4u;
                asm volatile(
                    "cp.async.bulk.shared::cluster.global.mbarrier::complete_tx::bytes"
                    " [%0], [%1], %2, [%3];"
                    :: "r"(d0), "l"(pbs[k] + (size_t)rA * W_IN),
                       "r"((uint32_t)(2 * W_IN * 4)), "r"(mba) : "memory");
            }
        } else {
#pragma unroll
            for (int k = 0; k < 4; ++k) {
                uint32_t d0 = smem_u32
                    + (uint32_t)(slot * SLOTF + k * (2 * W_IN)) * 4u;
                uint32_t d1 = d0 + (uint32_t)W_IN * 4u;
                asm volatile(
                    "cp.async.bulk.shared::cluster.global.mbarrier::complete_tx::bytes"
                    " [%0], [%1], %2, [%3];"
                    :: "r"(d0), "l"(pbs[k] + (size_t)rA * W_IN),
                       "r"((uint32_t)(W_IN * 4)), "r"(mba) : "memory");
                asm volatile(
                    "cp.async.bulk.shared::cluster.global.mbarrier::complete_tx::bytes"
                    " [%0], [%1], %2, [%3];"
                    :: "r"(d1), "l"(pbs[k] + (size_t)rB * W_IN),
                       "r"((uint32_t)(W_IN * 4)), "r"(mba) : "memory");
            }
        }
    };

    auto waitstage = [&](int p) {
        const uint32_t mba = mb_u32 + 8 * (p & 3);
        const uint32_t par = (uint32_t)((p >> 2) & 1);
        uint32_t done;
        asm volatile(
            "{\n\t.reg .pred P;\n\t"
            "mbarrier.try_wait.parity.shared.b64 P, [%1], %2;\n\t"
            "selp.b32 %0, 1, 0, P;\n\t}"
            : "=r"(done) : "r"(mba), "r"(par) : "memory");
        while (!done) {
            asm volatile(
                "{\n\t.reg .pred P;\n\t"
                "mbarrier.try_wait.parity.shared.b64 P, [%1], %2, 0x989680;\n\t"
                "selp.b32 %0, 1, 0, P;\n\t}"
                : "=r"(done) : "r"(mba), "r"(par) : "memory");
        }
    };

    // Band k, row-half RH lives at slot*SLOTF + k*1024 + RH*512.
#define BUILD(W, SLOT, RH) do {                                                \
    const float* base_ = &sm[(SLOT) * SLOTF + (RH) * W_IN];                    \
    const float* r0_ = base_;                                                  \
    const float* r1_ = base_ + 2 * W_IN;                                       \
    const float* r2_ = base_ + 4 * W_IN;                                       \
    const float* r3_ = base_ + 6 * W_IN;                                       \
    float2 v0 = *(const float2*)(r0_ + x2); float v0m = r0_[xm], v0p = r0_[xp];\
    float2 v1 = *(const float2*)(r1_ + x2); float v1m = r1_[xm], v1p = r1_[xp];\
    float2 v2 = *(const float2*)(r2_ + x2); float v2m = r2_[xm], v2p = r2_[xp];\
    float2 v3 = *(const float2*)(r3_ + x2); float v3m = r3_[xm], v3p = r3_[xp];\
    float lhe0a = xe ? v0.x : (v0m + v0.x);                                    \
    float lhe0b = v0.x + v0.y;                                                 \
    float lho0a = fmaf(6.f, v0.x, v0m + v0.y);                                 \
    float lho0b = fmaf(6.f, v0.y, v0.x + v0p);                                 \
    float ghe2a = xe ? (-2.f * v2.x) : (v2m - v2.x);                           \
    float ghe2b = v2.x - v2.y;                                                 \
    float gho2a = v2m - v2.y;                                                  \
    float gho2b = v2.x - v2p;                                                  \
    Pe[W][0] = fmaf(wPle, lhe0a, wPge * ghe2a);                                \
    Pe[W][1] = fmaf(wPle, lhe0b, wPge * ghe2b);                                \
    Po[W][0] = fmaf(wPlo, lho0a, wPgo * gho2a);                                \
    Po[W][1] = fmaf(wPlo, lho0b, wPgo * gho2b);                                \
    float lhe1a = xe ? v1.x : (v1m + v1.x);                                    \
    float lhe1b = v1.x + v1.y;                                                 \
    float lho1a = fmaf(6.f, v1.x, v1m + v1.y);                                 \
    float lho1b = fmaf(6.f, v1.y, v1.x + v1p);                                 \
    float ghe3a = xe ? (-2.f * v3.x) : (v3m - v3.x);                           \
    float ghe3b = v3.x - v3.y;                                                 \
    float gho3a = v3m - v3.y;                                                  \
    float gho3b = v3.x - v3p;                                                  \
    Qe[W][0] = fmaf(wQle, lhe1a, wQge * ghe3a);                                \
    Qe[W][1] = fmaf(wQle, lhe1b, wQge * ghe3b);                                \
    Qo[W][0] = fmaf(wQlo, lho1a, wQgo * gho3a);                                \
    Qo[W][1] = fmaf(wQlo, lho1b, wQgo * gho3b);                                \
} while (0)

    auto emit = [&](int y, bool top) {
        float oee[2], oeo[2], ooe[2], ooo[2];
#pragma unroll
        for (int c = 0; c < 2; ++c) {
            if (top) {
                oee[c] = Pe[1][c] - Qe[1][c];
                oeo[c] = Po[1][c] - Qo[1][c];
            } else {
                oee[c] = fmaf(0.5f, Qe[0][c] - Qe[1][c], Pe[0][c] + Pe[1][c]);
                oeo[c] = fmaf(0.5f, Qo[0][c] - Qo[1][c], Po[0][c] + Po[1][c]);
            }
            ooe[c] = 0.25f * (fmaf(6.f, Pe[1][c], Pe[0][c] + Pe[2][c])
                              + (Qe[0][c] - Qe[2][c]));
            ooo[c] = 0.25f * (fmaf(6.f, Po[1][c], Po[0][c] + Po[2][c])
                              + (Qo[0][c] - Qo[2][c]));
        }
        float* o0 = op + (size_t)(2 * y) * 1024 + 4 * tx;
        *(float4*)(o0)        = make_float4(oee[0], oeo[0], oee[1], oeo[1]);
        *(float4*)(o0 + 1024) = make_float4(ooe[0], ooo[0], ooe[1], ooo[1]);
    };

    auto shiftw = [&]() {
#pragma unroll
        for (int c = 0; c < 2; ++c) {
            Pe[0][c] = Pe[1][c]; Pe[1][c] = Pe[2][c];
            Po[0][c] = Po[1][c]; Po[1][c] = Po[2][c];
            Qe[0][c] = Qe[1][c]; Qe[1][c] = Qe[2][c];
            Qo[0][c] = Qo[1][c]; Qo[1][c] = Qo[2][c];
        }
    };

    // ---- prologue: stages 0,1,2 in flight; consume stage 0 (rows y0-1, y0)
    issue(0);
    issue(1);
    issue(2);
    waitstage(0);
    BUILD(0, 0, 0);
    BUILD(1, 0, 1);

    const bool topstrip = (y0 == 0);

    for (int p = 1; p <= NP; ++p) {
        waitstage(p);

        const int slot = p & 3;
        const int y = y0 + 2 * p - 2;

        BUILD(2, slot, 0);
        emit(y, topstrip && (p == 1));
        shiftw();

        BUILD(2, slot, 1);
        emit(y + 1, false);
        shiftw();

        __syncthreads();
        // All threads' reads of slot (p-2)&3 (== (p+2)&3) are now complete.
        if (p + 2 <= NP) issue(p + 2);
    }
#undef BUILD
}

extern "C" void kernel_launch(void* const* d_in, const int* in_sizes, int n_in,
                              void* d_out, int out_size)
{
    int ix = 0;
    for (int i = 0; i < n_in; ++i)
        if (in_sizes[i] > 64) { ix = i; break; }
    const float* xin = (const float*)d_in[ix];
    const float* f[4];
    int j = 0;
    for (int i = 0; i < n_in && j < 4; ++i)
        if (i != ix) f[j++] = (const float*)d_in[i];

    cudaFuncSetAttribute(ihaar_kernel,
                         cudaFuncAttributeMaxDynamicSharedMemorySize,
                         DEPTH * SLOTF * (int)sizeof(float));

    dim3 block(256, 1, 1);
    dim3 grid(1, H_IN / YS, 48);
    ihaar_kernel<<<grid, block, DEPTH * SLOTF * sizeof(float)>>>(
        xin, f[0], f[1], f[2], f[3], (float*)d_out);
}